// round 1
// baseline (speedup 1.0000x reference)
#include <cuda_runtime.h>

#define NB 64
#define SSTR 68              // padded row stride (floats), 16B aligned, conflict-friendly
#define BUF (NB * SSTR)

static __device__ float g_F[2][NB * NB];   // F_k = P @ Lh_k  (row-major)

// ---------------------------------------------------------------------------
// inner 64^3 matmul loop: acc[i][j] += sum_k A(i,k) * Bop(k,j)
// A_TRANS: A operand stored transposed in smem (As[k*SSTR + i], per-k contiguous)
//          else A row-major (As[i*SSTR + k], 4 scalar broadcast loads)
// B operand always layout [k*SSTR + j] (per-k contiguous, float4)
// FUSE: B := B + b2sc * B2   (same layout)
// ---------------------------------------------------------------------------
template<bool A_TRANS, bool FUSE>
__device__ __forceinline__ void mm_loop(const float* __restrict__ As,
                                        const float* __restrict__ Bs,
                                        const float* __restrict__ B2s, float b2sc,
                                        float acc[4][4], int ty4, int tx4)
{
#pragma unroll 4
    for (int k = 0; k < NB; ++k) {
        float a0, a1, a2, a3;
        if (A_TRANS) {
            float4 av = *(const float4*)(As + k * SSTR + ty4);
            a0 = av.x; a1 = av.y; a2 = av.z; a3 = av.w;
        } else {
            a0 = As[(ty4 + 0) * SSTR + k];
            a1 = As[(ty4 + 1) * SSTR + k];
            a2 = As[(ty4 + 2) * SSTR + k];
            a3 = As[(ty4 + 3) * SSTR + k];
        }
        float4 bv = *(const float4*)(Bs + k * SSTR + tx4);
        if (FUSE) {
            float4 b2 = *(const float4*)(B2s + k * SSTR + tx4);
            bv.x = fmaf(b2sc, b2.x, bv.x);
            bv.y = fmaf(b2sc, b2.y, bv.y);
            bv.z = fmaf(b2sc, b2.z, bv.z);
            bv.w = fmaf(b2sc, b2.w, bv.w);
        }
        acc[0][0] = fmaf(a0, bv.x, acc[0][0]);
        acc[0][1] = fmaf(a0, bv.y, acc[0][1]);
        acc[0][2] = fmaf(a0, bv.z, acc[0][2]);
        acc[0][3] = fmaf(a0, bv.w, acc[0][3]);
        acc[1][0] = fmaf(a1, bv.x, acc[1][0]);
        acc[1][1] = fmaf(a1, bv.y, acc[1][1]);
        acc[1][2] = fmaf(a1, bv.z, acc[1][2]);
        acc[1][3] = fmaf(a1, bv.w, acc[1][3]);
        acc[2][0] = fmaf(a2, bv.x, acc[2][0]);
        acc[2][1] = fmaf(a2, bv.y, acc[2][1]);
        acc[2][2] = fmaf(a2, bv.z, acc[2][2]);
        acc[2][3] = fmaf(a2, bv.w, acc[2][3]);
        acc[3][0] = fmaf(a3, bv.x, acc[3][0]);
        acc[3][1] = fmaf(a3, bv.y, acc[3][1]);
        acc[3][2] = fmaf(a3, bv.z, acc[3][2]);
        acc[3][3] = fmaf(a3, bv.w, acc[3][3]);
    }
}

// emode: 0 = store (stride SSTR), 1 = accumulate (stride SSTR),
//        2 = transposed scalar store (stride SSTR), 3 = store row-major stride NB (global)
template<bool A_TRANS>
__device__ __forceinline__ void do_mm(const float* __restrict__ As,
                                      const float* __restrict__ Bs,
                                      const float* __restrict__ B2s, float b2sc,
                                      float* __restrict__ Out, int emode)
{
    const int tid = threadIdx.x;
    const int tx4 = (tid & 15) * 4;
    const int ty4 = (tid >> 4) * 4;
    float acc[4][4] = {};
    if (B2s)
        mm_loop<A_TRANS, true>(As, Bs, B2s, b2sc, acc, ty4, tx4);
    else
        mm_loop<A_TRANS, false>(As, Bs, nullptr, 0.f, acc, ty4, tx4);

    if (emode == 2) {
#pragma unroll
        for (int i = 0; i < 4; ++i)
#pragma unroll
            for (int j = 0; j < 4; ++j)
                Out[(tx4 + j) * SSTR + (ty4 + i)] = acc[i][j];
    } else if (emode == 3) {
#pragma unroll
        for (int i = 0; i < 4; ++i)
            *(float4*)(Out + (ty4 + i) * NB + tx4) =
                make_float4(acc[i][0], acc[i][1], acc[i][2], acc[i][3]);
    } else {
#pragma unroll
        for (int i = 0; i < 4; ++i) {
            float4* p = (float4*)(Out + (ty4 + i) * SSTR + tx4);
            float4 v = make_float4(acc[i][0], acc[i][1], acc[i][2], acc[i][3]);
            if (emode == 1) {
                float4 o = *p;
                v.x += o.x; v.y += o.y; v.z += o.z; v.w += o.w;
            }
            *p = v;
        }
    }
}

// copy 64x64 row-major global -> smem (stride SSTR), coalesced float4
__device__ __forceinline__ void load_rm(float* __restrict__ dst,
                                        const float* __restrict__ g, int tid)
{
#pragma unroll
    for (int e = tid * 4; e < NB * NB; e += 1024)
        *(float4*)(dst + (e >> 6) * SSTR + (e & 63)) = *(const float4*)(g + e);
}

// stage constant 64x64 row-major global -> smem TRANSPOSED (MC[k*SSTR+i] = M[i][k])
// mapping chosen so global loads are coalesced and STS.128 is bank-conflict-free
__device__ __forceinline__ void load_const_T(float* __restrict__ MC,
                                             const float* __restrict__ gM, int tid)
{
#pragma unroll
    for (int it = 0; it < 4; ++it) {
        int idx = it * 256 + tid;          // 0..1023
        int k  = idx & 63;
        int i4 = (idx >> 6) << 2;
        float v0 = gM[(i4 + 0) * NB + k];
        float v1 = gM[(i4 + 1) * NB + k];
        float v2 = gM[(i4 + 2) * NB + k];
        float v3 = gM[(i4 + 3) * NB + k];
        *(float4*)(MC + k * SSTR + i4) = make_float4(v0, v1, v2, v3);
    }
}

// ---------------------------------------------------------------------------
// precompute kernel: P = U_one @ (I + W + W^2), W = I - U_half ; F_k = P @ Lh_k
// single CTA, negligible cost
// ---------------------------------------------------------------------------
__global__ void __launch_bounds__(256, 1)
krk_pre(const float* __restrict__ U_half,
        const float* __restrict__ U_one,
        const float* __restrict__ Lh)
{
    extern __shared__ float sm[];
    float* Wt = sm;              // W transposed / later U_one^T
    float* Wr = sm + BUF;        // W row-major / Winv / Lh tile
    float* Cc = sm + 2 * BUF;    // W2 / P^T
    const int tid = threadIdx.x;

    for (int e = tid; e < NB * NB; e += 256) {
        int i = e >> 6, j = e & 63;
        float w = ((i == j) ? 1.f : 0.f) - U_half[e];
        Wr[i * SSTR + j] = w;
        Wt[j * SSTR + i] = w;
    }
    __syncthreads();
    do_mm<true>(Wt, Wr, nullptr, 0.f, Cc, 0);          // Cc = W @ W  (row-major)
    __syncthreads();
    for (int e = tid; e < NB * NB; e += 256) {
        int i = e >> 6, j = e & 63;
        int idx = i * SSTR + j;
        Wr[idx] = ((i == j) ? 1.f : 0.f) + Wr[idx] + Cc[idx];   // Winv = I + W + W2
        Wt[j * SSTR + i] = U_one[e];                            // U_one^T
    }
    __syncthreads();
    do_mm<true>(Wt, Wr, nullptr, 0.f, Cc, 2);          // Cc = P^T (transposed store)
    __syncthreads();
    for (int kk = 0; kk < 2; ++kk) {
        load_rm(Wr, Lh + kk * NB * NB, tid);
        __syncthreads();
        do_mm<true>(Cc, Wr, nullptr, 0.f, &g_F[kk][0], 3);   // g_F[kk] = P @ Lh_k
        __syncthreads();
    }
}

// ---------------------------------------------------------------------------
// main kernel: one CTA per density matrix, whole chain in SMEM
// ---------------------------------------------------------------------------
__global__ void __launch_bounds__(256, 2)
krk_main(const float* __restrict__ rho0,
         const float* __restrict__ U_half,
         const float* __restrict__ U_one,
         const float* __restrict__ L0,
         const float* __restrict__ L1,
         float* __restrict__ out)
{
    extern __shared__ float sm[];
    float* R0 = sm;              // rho0, later T = U1 D0 U1^T
    float* TA = sm + 1 * BUF;    // scratch (M @ X)
    float* BD = sm + 2 * BUF;    // D0 -> PDP -> D1
    float* ST = sm + 3 * BUF;    // rho1 -> rho2
    float* SB = sm + 4 * BUF;    // S -> out accumulator
    float* MC = sm + 5 * BUF;    // staged constant (transposed)
    const int tid = threadIdx.x;
    const int b = blockIdx.x;
    const float dt = 0.01f;

    load_rm(R0, rho0 + b * (NB * NB), tid);

    // stage table: const, X operand, out, emode
    const float* cptr[9] = { L0, L0 + NB * NB, U_half, U_one, U_one,
                             &g_F[0][0], &g_F[1][0], L1, L1 + NB * NB };
    const float* xptr[9] = { R0, R0, R0, R0, BD, ST, ST, ST, ST };
    float*       optr[9] = { BD, BD, ST, SB, R0, BD, BD, BD, BD };
    const int    em[9]   = { 0, 1, 0, 0, 0, 0, 1, 0, 1 };

    for (int s = 0; s < 9; ++s) {
        load_const_T(MC, cptr[s], tid);
        __syncthreads();
        const float* b2 = (s == 2) ? BD : nullptr;       // rho1: X = rho0 + 0.005*D0
        do_mm<true>(MC, xptr[s], b2, 0.5f * dt, TA, 0);  // TA = M @ X        (row-major)
        __syncthreads();
        do_mm<false>(TA, MC, nullptr, 0.f, optr[s], em[s]); // out = TA @ M^T
        __syncthreads();

        if (s == 6) {
            // E1: rho2 = S + dt*PDP -> ST ; out-partial = S + dt/6*T + 2dt/3*PDP -> SB
            const float c1 = dt / 6.0f, c2 = 2.0f * dt / 3.0f;
#pragma unroll
            for (int e = tid * 4; e < NB * NB; e += 1024) {
                int idx = (e >> 6) * SSTR + (e & 63);
                float4 sv = *(float4*)(SB + idx);
                float4 dv = *(float4*)(BD + idx);
                float4 tv = *(float4*)(R0 + idx);
                float4 r2, ob;
                r2.x = fmaf(dt, dv.x, sv.x);
                r2.y = fmaf(dt, dv.y, sv.y);
                r2.z = fmaf(dt, dv.z, sv.z);
                r2.w = fmaf(dt, dv.w, sv.w);
                ob.x = sv.x + c1 * tv.x + c2 * dv.x;
                ob.y = sv.y + c1 * tv.y + c2 * dv.y;
                ob.z = sv.z + c1 * tv.z + c2 * dv.z;
                ob.w = sv.w + c1 * tv.w + c2 * dv.w;
                *(float4*)(ST + idx) = r2;
                *(float4*)(SB + idx) = ob;
            }
            __syncthreads();
        }
    }

    // final: out = SB + dt/6 * D1
    {
        const float c1 = dt / 6.0f;
        float* og = out + b * (NB * NB);
#pragma unroll
        for (int e = tid * 4; e < NB * NB; e += 1024) {
            int idx = (e >> 6) * SSTR + (e & 63);
            float4 sv = *(float4*)(SB + idx);
            float4 dv = *(float4*)(BD + idx);
            float4 o;
            o.x = fmaf(c1, dv.x, sv.x);
            o.y = fmaf(c1, dv.y, sv.y);
            o.z = fmaf(c1, dv.z, sv.z);
            o.w = fmaf(c1, dv.w, sv.w);
            *(float4*)(og + e) = o;
        }
    }
}

extern "C" void kernel_launch(void* const* d_in, const int* in_sizes, int n_in,
                              void* d_out, int out_size)
{
    const float* rho0   = (const float*)d_in[0];
    const float* U_half = (const float*)d_in[1];
    const float* U_one  = (const float*)d_in[2];
    const float* L0     = (const float*)d_in[3];
    const float* Lh     = (const float*)d_in[4];
    const float* L1     = (const float*)d_in[5];
    float* out = (float*)d_out;

    const int Bn = in_sizes[0] / (NB * NB);

    cudaFuncSetAttribute(krk_pre,  cudaFuncAttributeMaxDynamicSharedMemorySize, 3 * BUF * 4);
    cudaFuncSetAttribute(krk_main, cudaFuncAttributeMaxDynamicSharedMemorySize, 6 * BUF * 4);

    krk_pre<<<1, 256, 3 * BUF * 4>>>(U_half, U_one, Lh);
    krk_main<<<Bn, 256, 6 * BUF * 4>>>(rho0, U_half, U_one, L0, L1, out);
}

// round 2
// speedup vs baseline: 1.2951x; 1.2951x over previous
#include <cuda_runtime.h>

#define NB 64
#define SSTR 68              // padded row stride (floats)
#define BUF (NB * SSTR)

static __device__ float g_F[2][NB * NB];   // F_k = P @ Lh_k  (row-major)

// ---------------- f32x2 packed helpers ----------------
__device__ __forceinline__ unsigned long long pk2(float x) {
    unsigned long long r; unsigned u = __float_as_uint(x);
    asm("mov.b64 %0, {%1,%1};" : "=l"(r) : "r"(u));
    return r;
}
__device__ __forceinline__ void fma2(unsigned long long& d,
                                     unsigned long long a, unsigned long long b) {
    asm("fma.rn.f32x2 %0, %1, %2, %3;" : "=l"(d) : "l"(a), "l"(b), "l"(d));
}
__device__ __forceinline__ float2 unpk(unsigned long long v) {
    unsigned lo, hi;
    asm("mov.b64 {%0,%1}, %2;" : "=r"(lo), "=r"(hi) : "l"(v));
    return make_float2(__uint_as_float(lo), __uint_as_float(hi));
}

// ---------------------------------------------------------------------------
// scalar matmul (used only by the tiny precompute kernel)
// ---------------------------------------------------------------------------
template<bool A_TRANS>
__device__ __forceinline__ void do_mm(const float* __restrict__ As,
                                      const float* __restrict__ Bs,
                                      float* __restrict__ Out, int emode)
{
    const int tid = threadIdx.x;
    const int tx4 = (tid & 15) * 4;
    const int ty4 = (tid >> 4) * 4;
    float acc[4][4] = {};
#pragma unroll 4
    for (int k = 0; k < NB; ++k) {
        float a0, a1, a2, a3;
        if (A_TRANS) {
            float4 av = *(const float4*)(As + k * SSTR + ty4);
            a0 = av.x; a1 = av.y; a2 = av.z; a3 = av.w;
        } else {
            a0 = As[(ty4 + 0) * SSTR + k];
            a1 = As[(ty4 + 1) * SSTR + k];
            a2 = As[(ty4 + 2) * SSTR + k];
            a3 = As[(ty4 + 3) * SSTR + k];
        }
        float4 bv = *(const float4*)(Bs + k * SSTR + tx4);
#pragma unroll
        for (int j = 0; j < 4; ++j) {
            float b = (&bv.x)[j];
            acc[0][j] = fmaf(a0, b, acc[0][j]);
            acc[1][j] = fmaf(a1, b, acc[1][j]);
            acc[2][j] = fmaf(a2, b, acc[2][j]);
            acc[3][j] = fmaf(a3, b, acc[3][j]);
        }
    }
    if (emode == 2) {
#pragma unroll
        for (int i = 0; i < 4; ++i)
#pragma unroll
            for (int j = 0; j < 4; ++j)
                Out[(tx4 + j) * SSTR + (ty4 + i)] = acc[i][j];
    } else if (emode == 3) {
#pragma unroll
        for (int i = 0; i < 4; ++i)
            *(float4*)(Out + (ty4 + i) * NB + tx4) =
                make_float4(acc[i][0], acc[i][1], acc[i][2], acc[i][3]);
    } else {
#pragma unroll
        for (int i = 0; i < 4; ++i)
            *(float4*)(Out + (ty4 + i) * SSTR + tx4) =
                make_float4(acc[i][0], acc[i][1], acc[i][2], acc[i][3]);
    }
}

// ---------------------------------------------------------------------------
// packed mm1: Out = M @ X   (A = const transposed in smem, row-paired acc)
// A float4 reinterprets as 2 ready f32x2 pairs; B needs 4 dup-packs per k.
// FUSE: B := B + b2sc * B2
// ---------------------------------------------------------------------------
template<bool FUSE>
__device__ __forceinline__ void mm1p(const float* __restrict__ As,
                                     const float* __restrict__ Bs,
                                     const float* __restrict__ B2s, float b2sc,
                                     float* __restrict__ Out)
{
    const int tid = threadIdx.x;
    const int tx4 = (tid & 15) * 4;
    const int ty4 = (tid >> 4) * 4;
    unsigned long long acc[2][4] = {};     // acc[p][j]: rows (ty4+2p, ty4+2p+1), col tx4+j
#pragma unroll 4
    for (int k = 0; k < NB; ++k) {
        ulonglong2 av = *(const ulonglong2*)(As + k * SSTR + ty4);  // (a0,a1),(a2,a3)
        float4 bv = *(const float4*)(Bs + k * SSTR + tx4);
        if (FUSE) {
            float4 b2 = *(const float4*)(B2s + k * SSTR + tx4);
            bv.x = fmaf(b2sc, b2.x, bv.x);
            bv.y = fmaf(b2sc, b2.y, bv.y);
            bv.z = fmaf(b2sc, b2.z, bv.z);
            bv.w = fmaf(b2sc, b2.w, bv.w);
        }
        unsigned long long bx = pk2(bv.x), by = pk2(bv.y),
                           bz = pk2(bv.z), bw = pk2(bv.w);
        fma2(acc[0][0], av.x, bx);
        fma2(acc[0][1], av.x, by);
        fma2(acc[0][2], av.x, bz);
        fma2(acc[0][3], av.x, bw);
        fma2(acc[1][0], av.y, bx);
        fma2(acc[1][1], av.y, by);
        fma2(acc[1][2], av.y, bz);
        fma2(acc[1][3], av.y, bw);
    }
#pragma unroll
    for (int p = 0; p < 2; ++p) {
        float2 c0 = unpk(acc[p][0]);
        float2 c1 = unpk(acc[p][1]);
        float2 c2 = unpk(acc[p][2]);
        float2 c3 = unpk(acc[p][3]);
        *(float4*)(Out + (ty4 + 2 * p + 0) * SSTR + tx4) =
            make_float4(c0.x, c1.x, c2.x, c3.x);
        *(float4*)(Out + (ty4 + 2 * p + 1) * SSTR + tx4) =
            make_float4(c0.y, c1.y, c2.y, c3.y);
    }
}

// ---------------------------------------------------------------------------
// packed mm2: Out (+)= TA @ M^T  (A = TA row-major scalar-broadcast, col-paired acc)
// B float4 reinterprets as 2 ready f32x2 pairs; A needs 4 dup-packs per k.
// ACCUM: add into Out
// ---------------------------------------------------------------------------
template<bool ACCUM>
__device__ __forceinline__ void mm2p(const float* __restrict__ As,
                                     const float* __restrict__ Bs,
                                     float* __restrict__ Out)
{
    const int tid = threadIdx.x;
    const int tx4 = (tid & 15) * 4;
    const int ty4 = (tid >> 4) * 4;
    unsigned long long acc[4][2] = {};     // acc[i][q]: row ty4+i, cols (tx4+2q, tx4+2q+1)
#pragma unroll 4
    for (int k = 0; k < NB; ++k) {
        unsigned long long a0 = pk2(As[(ty4 + 0) * SSTR + k]);
        unsigned long long a1 = pk2(As[(ty4 + 1) * SSTR + k]);
        unsigned long long a2 = pk2(As[(ty4 + 2) * SSTR + k]);
        unsigned long long a3 = pk2(As[(ty4 + 3) * SSTR + k]);
        ulonglong2 bv = *(const ulonglong2*)(Bs + k * SSTR + tx4);  // (b0,b1),(b2,b3)
        fma2(acc[0][0], a0, bv.x);
        fma2(acc[0][1], a0, bv.y);
        fma2(acc[1][0], a1, bv.x);
        fma2(acc[1][1], a1, bv.y);
        fma2(acc[2][0], a2, bv.x);
        fma2(acc[2][1], a2, bv.y);
        fma2(acc[3][0], a3, bv.x);
        fma2(acc[3][1], a3, bv.y);
    }
#pragma unroll
    for (int i = 0; i < 4; ++i) {
        float2 cl = unpk(acc[i][0]);
        float2 ch = unpk(acc[i][1]);
        float4 v = make_float4(cl.x, cl.y, ch.x, ch.y);
        float4* p = (float4*)(Out + (ty4 + i) * SSTR + tx4);
        if (ACCUM) {
            float4 o = *p;
            v.x += o.x; v.y += o.y; v.z += o.z; v.w += o.w;
        }
        *p = v;
    }
}

// copy 64x64 row-major global -> smem (stride SSTR), coalesced float4
__device__ __forceinline__ void load_rm(float* __restrict__ dst,
                                        const float* __restrict__ g, int tid)
{
#pragma unroll
    for (int e = tid * 4; e < NB * NB; e += 1024)
        *(float4*)(dst + (e >> 6) * SSTR + (e & 63)) = *(const float4*)(g + e);
}

// stage constant 64x64 row-major global -> smem TRANSPOSED (MC[k*SSTR+i] = M[i][k])
__device__ __forceinline__ void load_const_T(float* __restrict__ MC,
                                             const float* __restrict__ gM, int tid)
{
#pragma unroll
    for (int it = 0; it < 4; ++it) {
        int idx = it * 256 + tid;          // 0..1023
        int k  = idx & 63;
        int i4 = (idx >> 6) << 2;
        float v0 = gM[(i4 + 0) * NB + k];
        float v1 = gM[(i4 + 1) * NB + k];
        float v2 = gM[(i4 + 2) * NB + k];
        float v3 = gM[(i4 + 3) * NB + k];
        *(float4*)(MC + k * SSTR + i4) = make_float4(v0, v1, v2, v3);
    }
}

// ---------------------------------------------------------------------------
// precompute kernel: P = U_one @ (I + W + W^2), W = I - U_half ; F_k = P @ Lh_k
// ---------------------------------------------------------------------------
__global__ void __launch_bounds__(256, 1)
krk_pre(const float* __restrict__ U_half,
        const float* __restrict__ U_one,
        const float* __restrict__ Lh)
{
    extern __shared__ float sm[];
    float* Wt = sm;              // W transposed / later U_one^T
    float* Wr = sm + BUF;        // W row-major / Winv / Lh tile
    float* Cc = sm + 2 * BUF;    // W2 / P^T
    const int tid = threadIdx.x;

    for (int e = tid; e < NB * NB; e += 256) {
        int i = e >> 6, j = e & 63;
        float w = ((i == j) ? 1.f : 0.f) - U_half[e];
        Wr[i * SSTR + j] = w;
        Wt[j * SSTR + i] = w;
    }
    __syncthreads();
    do_mm<true>(Wt, Wr, Cc, 0);                        // Cc = W @ W  (row-major)
    __syncthreads();
    for (int e = tid; e < NB * NB; e += 256) {
        int i = e >> 6, j = e & 63;
        int idx = i * SSTR + j;
        Wr[idx] = ((i == j) ? 1.f : 0.f) + Wr[idx] + Cc[idx];   // Winv = I + W + W2
        Wt[j * SSTR + i] = U_one[e];                            // U_one^T
    }
    __syncthreads();
    do_mm<true>(Wt, Wr, Cc, 2);                        // Cc = P^T (transposed store)
    __syncthreads();
    for (int kk = 0; kk < 2; ++kk) {
        load_rm(Wr, Lh + kk * NB * NB, tid);
        __syncthreads();
        do_mm<true>(Cc, Wr, &g_F[kk][0], 3);           // g_F[kk] = P @ Lh_k
        __syncthreads();
    }
}

// ---------------------------------------------------------------------------
// main kernel: one CTA per density matrix, whole chain in SMEM
// ---------------------------------------------------------------------------
__global__ void __launch_bounds__(256, 2)
krk_main(const float* __restrict__ rho0,
         const float* __restrict__ U_half,
         const float* __restrict__ U_one,
         const float* __restrict__ L0,
         const float* __restrict__ L1,
         float* __restrict__ out)
{
    extern __shared__ float sm[];
    float* R0 = sm;              // rho0, later T = U1 D0 U1^T
    float* TA = sm + 1 * BUF;    // scratch (M @ X)
    float* BD = sm + 2 * BUF;    // D0 -> PDP -> D1
    float* ST = sm + 3 * BUF;    // rho1 -> rho2
    float* SB = sm + 4 * BUF;    // S -> out accumulator
    float* MC = sm + 5 * BUF;    // staged constant (transposed)
    const int tid = threadIdx.x;
    const int b = blockIdx.x;
    const float dt = 0.01f;

    load_rm(R0, rho0 + b * (NB * NB), tid);

    // stage table: const, X operand, out, accumulate-flag
    const float* cptr[9] = { L0, L0 + NB * NB, U_half, U_one, U_one,
                             &g_F[0][0], &g_F[1][0], L1, L1 + NB * NB };
    const float* xptr[9] = { R0, R0, R0, R0, BD, ST, ST, ST, ST };
    float*       optr[9] = { BD, BD, ST, SB, R0, BD, BD, BD, BD };
    const int    em[9]   = { 0, 1, 0, 0, 0, 0, 1, 0, 1 };

    for (int s = 0; s < 9; ++s) {
        load_const_T(MC, cptr[s], tid);
        __syncthreads();
        if (s == 2)
            mm1p<true>(MC, xptr[s], BD, 0.5f * dt, TA);   // X = rho0 + 0.005*D0
        else
            mm1p<false>(MC, xptr[s], nullptr, 0.f, TA);   // TA = M @ X
        __syncthreads();
        if (em[s]) mm2p<true>(TA, MC, optr[s]);           // out += TA @ M^T
        else       mm2p<false>(TA, MC, optr[s]);          // out  = TA @ M^T
        __syncthreads();

        if (s == 6) {
            // rho2 = S + dt*PDP -> ST ; out-partial = S + dt/6*T + 2dt/3*PDP -> SB
            const float c1 = dt / 6.0f, c2 = 2.0f * dt / 3.0f;
#pragma unroll
            for (int e = tid * 4; e < NB * NB; e += 1024) {
                int idx = (e >> 6) * SSTR + (e & 63);
                float4 sv = *(float4*)(SB + idx);
                float4 dv = *(float4*)(BD + idx);
                float4 tv = *(float4*)(R0 + idx);
                float4 r2, ob;
                r2.x = fmaf(dt, dv.x, sv.x);
                r2.y = fmaf(dt, dv.y, sv.y);
                r2.z = fmaf(dt, dv.z, sv.z);
                r2.w = fmaf(dt, dv.w, sv.w);
                ob.x = sv.x + c1 * tv.x + c2 * dv.x;
                ob.y = sv.y + c1 * tv.y + c2 * dv.y;
                ob.z = sv.z + c1 * tv.z + c2 * dv.z;
                ob.w = sv.w + c1 * tv.w + c2 * dv.w;
                *(float4*)(ST + idx) = r2;
                *(float4*)(SB + idx) = ob;
            }
            __syncthreads();
        }
    }

    // final: out = SB + dt/6 * D1
    {
        const float c1 = dt / 6.0f;
        float* og = out + b * (NB * NB);
#pragma unroll
        for (int e = tid * 4; e < NB * NB; e += 1024) {
            int idx = (e >> 6) * SSTR + (e & 63);
            float4 sv = *(float4*)(SB + idx);
            float4 dv = *(float4*)(BD + idx);
            float4 o;
            o.x = fmaf(c1, dv.x, sv.x);
            o.y = fmaf(c1, dv.y, sv.y);
            o.z = fmaf(c1, dv.z, sv.z);
            o.w = fmaf(c1, dv.w, sv.w);
            *(float4*)(og + e) = o;
        }
    }
}

extern "C" void kernel_launch(void* const* d_in, const int* in_sizes, int n_in,
                              void* d_out, int out_size)
{
    const float* rho0   = (const float*)d_in[0];
    const float* U_half = (const float*)d_in[1];
    const float* U_one  = (const float*)d_in[2];
    const float* L0     = (const float*)d_in[3];
    const float* Lh     = (const float*)d_in[4];
    const float* L1     = (const float*)d_in[5];
    float* out = (float*)d_out;

    const int Bn = in_sizes[0] / (NB * NB);

    cudaFuncSetAttribute(krk_pre,  cudaFuncAttributeMaxDynamicSharedMemorySize, 3 * BUF * 4);
    cudaFuncSetAttribute(krk_main, cudaFuncAttributeMaxDynamicSharedMemorySize, 6 * BUF * 4);

    krk_pre<<<1, 256, 3 * BUF * 4>>>(U_half, U_one, Lh);
    krk_main<<<Bn, 256, 6 * BUF * 4>>>(rho0, U_half, U_one, L0, L1, out);
}

// round 3
// speedup vs baseline: 1.3135x; 1.0142x over previous
#include <cuda_runtime.h>

#define NB 64
#define SSTR 68              // padded row stride (floats)
#define BUF (NB * SSTR)

static __device__ float g_F[2][NB * NB];   // F_k = P @ Lh_k  (row-major)

// ---------------- f32x2 packed helpers ----------------
__device__ __forceinline__ unsigned long long pk2(float x) {
    unsigned long long r; unsigned u = __float_as_uint(x);
    asm("mov.b64 %0, {%1,%1};" : "=l"(r) : "r"(u));
    return r;
}
__device__ __forceinline__ void fma2(unsigned long long& d,
                                     unsigned long long a, unsigned long long b) {
    asm("fma.rn.f32x2 %0, %1, %2, %3;" : "=l"(d) : "l"(a), "l"(b), "l"(d));
}
__device__ __forceinline__ float2 unpk(unsigned long long v) {
    unsigned lo, hi;
    asm("mov.b64 {%0,%1}, %2;" : "=r"(lo), "=r"(hi) : "l"(v));
    return make_float2(__uint_as_float(lo), __uint_as_float(hi));
}

// ---------------------------------------------------------------------------
// scalar matmul (used only by the tiny precompute kernel; own tid mapping)
// ---------------------------------------------------------------------------
template<bool A_TRANS>
__device__ __forceinline__ void do_mm(const float* __restrict__ As,
                                      const float* __restrict__ Bs,
                                      float* __restrict__ Out, int emode)
{
    const int tid = threadIdx.x;
    const int tx4 = (tid & 15) * 4;
    const int ty4 = (tid >> 4) * 4;
    float acc[4][4] = {};
#pragma unroll 4
    for (int k = 0; k < NB; ++k) {
        float a0, a1, a2, a3;
        if (A_TRANS) {
            float4 av = *(const float4*)(As + k * SSTR + ty4);
            a0 = av.x; a1 = av.y; a2 = av.z; a3 = av.w;
        } else {
            a0 = As[(ty4 + 0) * SSTR + k];
            a1 = As[(ty4 + 1) * SSTR + k];
            a2 = As[(ty4 + 2) * SSTR + k];
            a3 = As[(ty4 + 3) * SSTR + k];
        }
        float4 bv = *(const float4*)(Bs + k * SSTR + tx4);
#pragma unroll
        for (int j = 0; j < 4; ++j) {
            float b = (&bv.x)[j];
            acc[0][j] = fmaf(a0, b, acc[0][j]);
            acc[1][j] = fmaf(a1, b, acc[1][j]);
            acc[2][j] = fmaf(a2, b, acc[2][j]);
            acc[3][j] = fmaf(a3, b, acc[3][j]);
        }
    }
    if (emode == 2) {
#pragma unroll
        for (int i = 0; i < 4; ++i)
#pragma unroll
            for (int j = 0; j < 4; ++j)
                Out[(tx4 + j) * SSTR + (ty4 + i)] = acc[i][j];
    } else if (emode == 3) {
#pragma unroll
        for (int i = 0; i < 4; ++i)
            *(float4*)(Out + (ty4 + i) * NB + tx4) =
                make_float4(acc[i][0], acc[i][1], acc[i][2], acc[i][3]);
    } else {
#pragma unroll
        for (int i = 0; i < 4; ++i)
            *(float4*)(Out + (ty4 + i) * SSTR + tx4) =
                make_float4(acc[i][0], acc[i][1], acc[i][2], acc[i][3]);
    }
}

// ---------------------------------------------------------------------------
// unified packed mm: Out(i,j) = sum_k A[k*SSTR+i] * B[k*SSTR+j]
// Both operands k-contiguous. Rows paired into f32x2 via the A float4 load.
// OMODE: 0 = row-major store, 1 = row-major accumulate, 2 = transposed store
//        (direct STS.64 of the row-pair accumulators, no unpack needed)
// FUSE: B := B + b2sc * B2
// Warp tile: 32 rows x 16 cols (lane r = lane>>2, c = lane&3) so the warp's
// A load is 128 contiguous bytes (1 wavefront) and B is 64 bytes (1 wavefront).
// ---------------------------------------------------------------------------
template<bool FUSE, int OMODE>
__device__ __forceinline__ void mm_pk(const float* __restrict__ As,
                                      const float* __restrict__ Bs,
                                      const float* __restrict__ B2s, float b2sc,
                                      float* __restrict__ Out,
                                      int ty4, int tx4)
{
    unsigned long long acc[2][4] = {};   // acc[p][j]: rows (ty4+2p, ty4+2p+1), col tx4+j
#pragma unroll 4
    for (int k = 0; k < NB; ++k) {
        ulonglong2 av = *(const ulonglong2*)(As + k * SSTR + ty4);
        float4 bv = *(const float4*)(Bs + k * SSTR + tx4);
        if (FUSE) {
            float4 b2 = *(const float4*)(B2s + k * SSTR + tx4);
            bv.x = fmaf(b2sc, b2.x, bv.x);
            bv.y = fmaf(b2sc, b2.y, bv.y);
            bv.z = fmaf(b2sc, b2.z, bv.z);
            bv.w = fmaf(b2sc, b2.w, bv.w);
        }
        unsigned long long bx = pk2(bv.x), by = pk2(bv.y),
                           bz = pk2(bv.z), bw = pk2(bv.w);
        fma2(acc[0][0], av.x, bx);
        fma2(acc[0][1], av.x, by);
        fma2(acc[0][2], av.x, bz);
        fma2(acc[0][3], av.x, bw);
        fma2(acc[1][0], av.y, bx);
        fma2(acc[1][1], av.y, by);
        fma2(acc[1][2], av.y, bz);
        fma2(acc[1][3], av.y, bw);
    }
    if (OMODE == 2) {
        // transposed store: Out[(tx4+j)*SSTR + ty4 + 2p] <- row-pair (f32x2) directly
#pragma unroll
        for (int j = 0; j < 4; ++j) {
            *(unsigned long long*)(Out + (tx4 + j) * SSTR + ty4 + 0) = acc[0][j];
            *(unsigned long long*)(Out + (tx4 + j) * SSTR + ty4 + 2) = acc[1][j];
        }
    } else {
#pragma unroll
        for (int p = 0; p < 2; ++p) {
            float2 c0 = unpk(acc[p][0]);
            float2 c1 = unpk(acc[p][1]);
            float2 c2 = unpk(acc[p][2]);
            float2 c3 = unpk(acc[p][3]);
            float4 v0 = make_float4(c0.x, c1.x, c2.x, c3.x);   // row ty4+2p
            float4 v1 = make_float4(c0.y, c1.y, c2.y, c3.y);   // row ty4+2p+1
            float4* p0 = (float4*)(Out + (ty4 + 2 * p + 0) * SSTR + tx4);
            float4* p1 = (float4*)(Out + (ty4 + 2 * p + 1) * SSTR + tx4);
            if (OMODE == 1) {
                float4 o0 = *p0, o1 = *p1;
                v0.x += o0.x; v0.y += o0.y; v0.z += o0.z; v0.w += o0.w;
                v1.x += o1.x; v1.y += o1.y; v1.z += o1.z; v1.w += o1.w;
            }
            *p0 = v0; *p1 = v1;
        }
    }
}

// copy 64x64 row-major global -> smem (stride SSTR), coalesced float4
__device__ __forceinline__ void load_rm(float* __restrict__ dst,
                                        const float* __restrict__ g, int tid)
{
#pragma unroll
    for (int e = tid * 4; e < NB * NB; e += 1024)
        *(float4*)(dst + (e >> 6) * SSTR + (e & 63)) = *(const float4*)(g + e);
}

// stage constant 64x64 row-major global -> smem TRANSPOSED (MC[k*SSTR+i] = M[i][k])
__device__ __forceinline__ void load_const_T(float* __restrict__ MC,
                                             const float* __restrict__ gM, int tid)
{
#pragma unroll
    for (int it = 0; it < 4; ++it) {
        int idx = it * 256 + tid;          // 0..1023
        int k  = idx & 63;
        int i4 = (idx >> 6) << 2;
        float v0 = gM[(i4 + 0) * NB + k];
        float v1 = gM[(i4 + 1) * NB + k];
        float v2 = gM[(i4 + 2) * NB + k];
        float v3 = gM[(i4 + 3) * NB + k];
        *(float4*)(MC + k * SSTR + i4) = make_float4(v0, v1, v2, v3);
    }
}

// ---------------------------------------------------------------------------
// precompute kernel: P = U_one @ (I + W + W^2), W = I - U_half ; F_k = P @ Lh_k
// ---------------------------------------------------------------------------
__global__ void __launch_bounds__(256, 1)
krk_pre(const float* __restrict__ U_half,
        const float* __restrict__ U_one,
        const float* __restrict__ Lh)
{
    extern __shared__ float sm[];
    float* Wt = sm;              // W transposed / later U_one^T
    float* Wr = sm + BUF;        // W row-major / Winv / Lh tile
    float* Cc = sm + 2 * BUF;    // W2 / P^T
    const int tid = threadIdx.x;

    for (int e = tid; e < NB * NB; e += 256) {
        int i = e >> 6, j = e & 63;
        float w = ((i == j) ? 1.f : 0.f) - U_half[e];
        Wr[i * SSTR + j] = w;
        Wt[j * SSTR + i] = w;
    }
    __syncthreads();
    do_mm<true>(Wt, Wr, Cc, 0);                        // Cc = W @ W  (row-major)
    __syncthreads();
    for (int e = tid; e < NB * NB; e += 256) {
        int i = e >> 6, j = e & 63;
        int idx = i * SSTR + j;
        Wr[idx] = ((i == j) ? 1.f : 0.f) + Wr[idx] + Cc[idx];   // Winv = I + W + W2
        Wt[j * SSTR + i] = U_one[e];                            // U_one^T
    }
    __syncthreads();
    do_mm<true>(Wt, Wr, Cc, 2);                        // Cc = P^T (transposed store)
    __syncthreads();
    for (int kk = 0; kk < 2; ++kk) {
        load_rm(Wr, Lh + kk * NB * NB, tid);
        __syncthreads();
        do_mm<true>(Cc, Wr, &g_F[kk][0], 3);           // g_F[kk] = P @ Lh_k
        __syncthreads();
    }
}

// ---------------------------------------------------------------------------
// main kernel: one CTA per density matrix, whole chain in SMEM
// ---------------------------------------------------------------------------
__global__ void __launch_bounds__(256, 2)
krk_main(const float* __restrict__ rho0,
         const float* __restrict__ U_half,
         const float* __restrict__ U_one,
         const float* __restrict__ L0,
         const float* __restrict__ L1,
         float* __restrict__ out)
{
    extern __shared__ float sm[];
    float* R0 = sm;              // rho0, later T = U1 D0 U1^T
    float* TAt = sm + 1 * BUF;   // scratch (M @ X) stored TRANSPOSED
    float* BD = sm + 2 * BUF;    // D0 -> PDP -> D1
    float* ST = sm + 3 * BUF;    // rho1 -> rho2
    float* SB = sm + 4 * BUF;    // S -> out accumulator
    float* MC = sm + 5 * BUF;    // staged constant (transposed)
    const int tid = threadIdx.x;
    const int b = blockIdx.x;
    const float dt = 0.01f;

    // warp tile 32 rows x 16 cols: warp's A load is 128 contiguous bytes
    const int lane = tid & 31, warp = tid >> 5;
    const int ty4 = ((warp & 1) << 5) + ((lane >> 2) << 2);   // row base
    const int tx4 = ((warp >> 1) << 4) + ((lane & 3) << 2);   // col base

    load_rm(R0, rho0 + b * (NB * NB), tid);

    // stage table: const, X operand, out, accumulate-flag
    const float* cptr[9] = { L0, L0 + NB * NB, U_half, U_one, U_one,
                             &g_F[0][0], &g_F[1][0], L1, L1 + NB * NB };
    const float* xptr[9] = { R0, R0, R0, R0, BD, ST, ST, ST, ST };
    float*       optr[9] = { BD, BD, ST, SB, R0, BD, BD, BD, BD };
    const int    em[9]   = { 0, 1, 0, 0, 0, 0, 1, 0, 1 };

    for (int s = 0; s < 9; ++s) {
        load_const_T(MC, cptr[s], tid);
        __syncthreads();
        // mm1: TAt = (M @ X)^T   (A = MC rows of M, B = X cols; store transposed)
        if (s == 2)
            mm_pk<true, 2>(MC, xptr[s], BD, 0.5f * dt, TAt, ty4, tx4);  // X = rho0 + 0.005*D0
        else
            mm_pk<false, 2>(MC, xptr[s], nullptr, 0.f, TAt, ty4, tx4);
        __syncthreads();
        // mm2: Out(i,j) (+)= sum_k TA[i][k] M[j][k] = sum_k TAt[k][i] MC[k][j]
        if (em[s]) mm_pk<false, 1>(TAt, MC, nullptr, 0.f, optr[s], ty4, tx4);
        else       mm_pk<false, 0>(TAt, MC, nullptr, 0.f, optr[s], ty4, tx4);
        __syncthreads();

        if (s == 6) {
            // rho2 = S + dt*PDP -> ST ; out-partial = S + dt/6*T + 2dt/3*PDP -> SB
            const float c1 = dt / 6.0f, c2 = 2.0f * dt / 3.0f;
#pragma unroll
            for (int e = tid * 4; e < NB * NB; e += 1024) {
                int idx = (e >> 6) * SSTR + (e & 63);
                float4 sv = *(float4*)(SB + idx);
                float4 dv = *(float4*)(BD + idx);
                float4 tv = *(float4*)(R0 + idx);
                float4 r2, ob;
                r2.x = fmaf(dt, dv.x, sv.x);
                r2.y = fmaf(dt, dv.y, sv.y);
                r2.z = fmaf(dt, dv.z, sv.z);
                r2.w = fmaf(dt, dv.w, sv.w);
                ob.x = sv.x + c1 * tv.x + c2 * dv.x;
                ob.y = sv.y + c1 * tv.y + c2 * dv.y;
                ob.z = sv.z + c1 * tv.z + c2 * dv.z;
                ob.w = sv.w + c1 * tv.w + c2 * dv.w;
                *(float4*)(ST + idx) = r2;
                *(float4*)(SB + idx) = ob;
            }
            __syncthreads();
        }
    }

    // final: out = SB + dt/6 * D1
    {
        const float c1 = dt / 6.0f;
        float* og = out + b * (NB * NB);
#pragma unroll
        for (int e = tid * 4; e < NB * NB; e += 1024) {
            int idx = (e >> 6) * SSTR + (e & 63);
            float4 sv = *(float4*)(SB + idx);
            float4 dv = *(float4*)(BD + idx);
            float4 o;
            o.x = fmaf(c1, dv.x, sv.x);
            o.y = fmaf(c1, dv.y, sv.y);
            o.z = fmaf(c1, dv.z, sv.z);
            o.w = fmaf(c1, dv.w, sv.w);
            *(float4*)(og + e) = o;
        }
    }
}

extern "C" void kernel_launch(void* const* d_in, const int* in_sizes, int n_in,
                              void* d_out, int out_size)
{
    const float* rho0   = (const float*)d_in[0];
    const float* U_half = (const float*)d_in[1];
    const float* U_one  = (const float*)d_in[2];
    const float* L0     = (const float*)d_in[3];
    const float* Lh     = (const float*)d_in[4];
    const float* L1     = (const float*)d_in[5];
    float* out = (float*)d_out;

    const int Bn = in_sizes[0] / (NB * NB);

    cudaFuncSetAttribute(krk_pre,  cudaFuncAttributeMaxDynamicSharedMemorySize, 3 * BUF * 4);
    cudaFuncSetAttribute(krk_main, cudaFuncAttributeMaxDynamicSharedMemorySize, 6 * BUF * 4);

    krk_pre<<<1, 256, 3 * BUF * 4>>>(U_half, U_one, Lh);
    krk_main<<<Bn, 256, 6 * BUF * 4>>>(rho0, U_half, U_one, L0, L1, out);
}

// round 4
// speedup vs baseline: 1.4948x; 1.1380x over previous
#include <cuda_runtime.h>

#define NB 64
#define SSTR 68              // padded row stride (floats); 272B rows, 16B-aligned
#define BUF (NB * SSTR)

static __device__ float g_F[2][NB * NB];   // F_k = P @ Lh_k  (row-major)

// ---------------- f32x2 packed helpers ----------------
__device__ __forceinline__ unsigned long long pk2(float x) {
    unsigned long long r; unsigned u = __float_as_uint(x);
    asm("mov.b64 %0, {%1,%1};" : "=l"(r) : "r"(u));
    return r;
}
__device__ __forceinline__ void fma2(unsigned long long& d,
                                     unsigned long long a, unsigned long long b) {
    asm("fma.rn.f32x2 %0, %1, %2, %3;" : "=l"(d) : "l"(a), "l"(b), "l"(d));
}
__device__ __forceinline__ float2 unpk(unsigned long long v) {
    unsigned lo, hi;
    asm("mov.b64 {%0,%1}, %2;" : "=r"(lo), "=r"(hi) : "l"(v));
    return make_float2(__uint_as_float(lo), __uint_as_float(hi));
}

// ---------------------------------------------------------------------------
// scalar matmul (used only by the tiny precompute kernel; own tid mapping)
// ---------------------------------------------------------------------------
template<bool A_TRANS>
__device__ __forceinline__ void do_mm(const float* __restrict__ As,
                                      const float* __restrict__ Bs,
                                      float* __restrict__ Out, int emode)
{
    const int tid = threadIdx.x;
    const int tx4 = (tid & 15) * 4;
    const int ty4 = (tid >> 4) * 4;
    float acc[4][4] = {};
#pragma unroll 4
    for (int k = 0; k < NB; ++k) {
        float a0, a1, a2, a3;
        if (A_TRANS) {
            float4 av = *(const float4*)(As + k * SSTR + ty4);
            a0 = av.x; a1 = av.y; a2 = av.z; a3 = av.w;
        } else {
            a0 = As[(ty4 + 0) * SSTR + k];
            a1 = As[(ty4 + 1) * SSTR + k];
            a2 = As[(ty4 + 2) * SSTR + k];
            a3 = As[(ty4 + 3) * SSTR + k];
        }
        float4 bv = *(const float4*)(Bs + k * SSTR + tx4);
#pragma unroll
        for (int j = 0; j < 4; ++j) {
            float b = (&bv.x)[j];
            acc[0][j] = fmaf(a0, b, acc[0][j]);
            acc[1][j] = fmaf(a1, b, acc[1][j]);
            acc[2][j] = fmaf(a2, b, acc[2][j]);
            acc[3][j] = fmaf(a3, b, acc[3][j]);
        }
    }
    if (emode == 2) {
#pragma unroll
        for (int i = 0; i < 4; ++i)
#pragma unroll
            for (int j = 0; j < 4; ++j)
                Out[(tx4 + j) * SSTR + (ty4 + i)] = acc[i][j];
    } else if (emode == 3) {
#pragma unroll
        for (int i = 0; i < 4; ++i)
            *(float4*)(Out + (ty4 + i) * NB + tx4) =
                make_float4(acc[i][0], acc[i][1], acc[i][2], acc[i][3]);
    } else {
#pragma unroll
        for (int i = 0; i < 4; ++i)
            *(float4*)(Out + (ty4 + i) * SSTR + tx4) =
                make_float4(acc[i][0], acc[i][1], acc[i][2], acc[i][3]);
    }
}

// ---------------------------------------------------------------------------
// main packed mm: Out(i,j) (+)= sum_k (A[k][i] + sc*A2[k][i]) * MC[k][j]
// Out stored ROW-MAJOR. A operand: rows ry..ry+7 (warp-uniform -> LDS broadcast),
// B operand: cols cx..cx+3 (identical across half-warps -> broadcast).
// Computes G^T when A=X, MC=M^T-layout: cell (i,j) = (M@X)^T[i][j] exactly.
// ---------------------------------------------------------------------------
template<bool FUSE, bool ACCUM>
__device__ __forceinline__ void mm8x4(const float* __restrict__ As,
                                      const float* __restrict__ A2s,
                                      const float* __restrict__ Bs,
                                      float* __restrict__ Out,
                                      int ry, int cx, float sc)
{
    unsigned long long acc[4][4] = {};   // acc[p][j]: rows (ry+2p, ry+2p+1), col cx+j
    const unsigned long long sc2 = pk2(sc);
#pragma unroll 4
    for (int k = 0; k < NB; ++k) {
        ulonglong2 a01 = *(const ulonglong2*)(As + k * SSTR + ry);
        ulonglong2 a23 = *(const ulonglong2*)(As + k * SSTR + ry + 4);
        if (FUSE) {
            ulonglong2 f01 = *(const ulonglong2*)(A2s + k * SSTR + ry);
            ulonglong2 f23 = *(const ulonglong2*)(A2s + k * SSTR + ry + 4);
            fma2(a01.x, sc2, f01.x);
            fma2(a01.y, sc2, f01.y);
            fma2(a23.x, sc2, f23.x);
            fma2(a23.y, sc2, f23.y);
        }
        float4 bv = *(const float4*)(Bs + k * SSTR + cx);
        unsigned long long b0 = pk2(bv.x), b1 = pk2(bv.y),
                           b2 = pk2(bv.z), b3 = pk2(bv.w);
        fma2(acc[0][0], a01.x, b0);
        fma2(acc[0][1], a01.x, b1);
        fma2(acc[0][2], a01.x, b2);
        fma2(acc[0][3], a01.x, b3);
        fma2(acc[1][0], a01.y, b0);
        fma2(acc[1][1], a01.y, b1);
        fma2(acc[1][2], a01.y, b2);
        fma2(acc[1][3], a01.y, b3);
        fma2(acc[2][0], a23.x, b0);
        fma2(acc[2][1], a23.x, b1);
        fma2(acc[2][2], a23.x, b2);
        fma2(acc[2][3], a23.x, b3);
        fma2(acc[3][0], a23.y, b0);
        fma2(acc[3][1], a23.y, b1);
        fma2(acc[3][2], a23.y, b2);
        fma2(acc[3][3], a23.y, b3);
    }
#pragma unroll
    for (int p = 0; p < 4; ++p) {
        float2 c0 = unpk(acc[p][0]);
        float2 c1 = unpk(acc[p][1]);
        float2 c2 = unpk(acc[p][2]);
        float2 c3 = unpk(acc[p][3]);
        float4 vlo = make_float4(c0.x, c1.x, c2.x, c3.x);   // row ry+2p
        float4 vhi = make_float4(c0.y, c1.y, c2.y, c3.y);   // row ry+2p+1
        float4* plo = (float4*)(Out + (ry + 2 * p + 0) * SSTR + cx);
        float4* phi = (float4*)(Out + (ry + 2 * p + 1) * SSTR + cx);
        if (ACCUM) {
            float4 o0 = *plo, o1 = *phi;
            vlo.x += o0.x; vlo.y += o0.y; vlo.z += o0.z; vlo.w += o0.w;
            vhi.x += o1.x; vhi.y += o1.y; vhi.z += o1.z; vhi.w += o1.w;
        }
        *plo = vlo; *phi = vhi;
    }
}

// copy 64x64 row-major global -> smem (stride SSTR), coalesced float4
__device__ __forceinline__ void load_rm(float* __restrict__ dst,
                                        const float* __restrict__ g, int tid)
{
#pragma unroll
    for (int e = tid * 4; e < NB * NB; e += 1024)
        *(float4*)(dst + (e >> 6) * SSTR + (e & 63)) = *(const float4*)(g + e);
}

// stage constant 64x64 row-major global -> smem TRANSPOSED (MC[k*SSTR+i] = M[i][k])
__device__ __forceinline__ void load_const_T(float* __restrict__ MC,
                                             const float* __restrict__ gM, int tid)
{
#pragma unroll
    for (int it = 0; it < 4; ++it) {
        int idx = it * 256 + tid;          // 0..1023
        int k  = idx & 63;
        int i4 = (idx >> 6) << 2;
        float v0 = gM[(i4 + 0) * NB + k];
        float v1 = gM[(i4 + 1) * NB + k];
        float v2 = gM[(i4 + 2) * NB + k];
        float v3 = gM[(i4 + 3) * NB + k];
        *(float4*)(MC + k * SSTR + i4) = make_float4(v0, v1, v2, v3);
    }
}

// ---------------------------------------------------------------------------
// precompute kernel: P = U_one @ (I + W + W^2), W = I - U_half ; F_k = P @ Lh_k
// ---------------------------------------------------------------------------
__global__ void __launch_bounds__(256, 1)
krk_pre(const float* __restrict__ U_half,
        const float* __restrict__ U_one,
        const float* __restrict__ Lh)
{
    extern __shared__ float sm[];
    float* Wt = sm;              // W transposed / later U_one^T
    float* Wr = sm + BUF;        // W row-major / Winv / Lh tile
    float* Cc = sm + 2 * BUF;    // W2 / P^T
    const int tid = threadIdx.x;

    for (int e = tid; e < NB * NB; e += 256) {
        int i = e >> 6, j = e & 63;
        float w = ((i == j) ? 1.f : 0.f) - U_half[e];
        Wr[i * SSTR + j] = w;
        Wt[j * SSTR + i] = w;
    }
    __syncthreads();
    do_mm<true>(Wt, Wr, Cc, 0);                        // Cc = W @ W  (row-major)
    __syncthreads();
    for (int e = tid; e < NB * NB; e += 256) {
        int i = e >> 6, j = e & 63;
        int idx = i * SSTR + j;
        Wr[idx] = ((i == j) ? 1.f : 0.f) + Wr[idx] + Cc[idx];   // Winv = I + W + W2
        Wt[j * SSTR + i] = U_one[e];                            // U_one^T
    }
    __syncthreads();
    do_mm<true>(Wt, Wr, Cc, 2);                        // Cc = P^T (transposed store)
    __syncthreads();
    for (int kk = 0; kk < 2; ++kk) {
        load_rm(Wr, Lh + kk * NB * NB, tid);
        __syncthreads();
        do_mm<true>(Cc, Wr, &g_F[kk][0], 3);           // g_F[kk] = P @ Lh_k
        __syncthreads();
    }
}

// ---------------------------------------------------------------------------
// main kernel: 2 density matrices per CTA (half-warp pairing), chain in SMEM
// buffers per matrix m: [R0, TAt, BD, ST, SB] at sm + m*5*BUF; MC shared.
// ---------------------------------------------------------------------------
__global__ void __launch_bounds__(256, 1)
krk_main(const float* __restrict__ rho0,
         const float* __restrict__ U_half,
         const float* __restrict__ U_one,
         const float* __restrict__ L0,
         const float* __restrict__ L1,
         float* __restrict__ out)
{
    extern __shared__ float sm[];
    const int tid = threadIdx.x;
    const int w = tid >> 5, l = tid & 31;
    const int h = l >> 4, lp = l & 15;      // half-warp selects matrix
    const int ry = w << 3;                  // 8-row block (warp-uniform)
    const int cx = lp << 2;                 // 4-col block
    float* mb = sm + h * 5 * BUF;           // this thread's matrix buffers
    float* MC = sm + 10 * BUF;
    const int b = blockIdx.x;               // handles rho 2b, 2b+1
    const float dt = 0.01f;

    for (int m = 0; m < 2; ++m)
        load_rm(sm + m * 5 * BUF, rho0 + (2 * b + m) * (NB * NB), tid);

    // buffer indices: 0=R0, 1=TAt, 2=BD, 3=ST, 4=SB
    const float* cptr[9] = { L0, L0 + NB * NB, U_half, U_one, U_one,
                             &g_F[0][0], &g_F[1][0], L1, L1 + NB * NB };
    const int xi[9] = { 0, 0, 0, 0, 2, 3, 3, 3, 3 };
    const int oi[9] = { 2, 2, 3, 4, 0, 2, 2, 2, 2 };
    const int em[9] = { 0, 1, 0, 0, 0, 0, 1, 0, 1 };

    for (int s = 0; s < 9; ++s) {
        load_const_T(MC, cptr[s], tid);
        __syncthreads();
        const float* As = mb + xi[s] * BUF;
        float* TAt = mb + BUF;
        // mm1: TAt[i][j] = sum_k X[k][i] * M[j][k] = (M@X)^T[i][j]  (exact)
        if (s == 2)
            mm8x4<true, false>(As, mb + 2 * BUF, MC, TAt, ry, cx, 0.5f * dt);
        else
            mm8x4<false, false>(As, nullptr, MC, TAt, ry, cx, 0.f);
        __syncthreads();
        // mm2: Out[i][j] (+)= sum_k TAt[k][i] * M[j][k] = (M@X@M^T)[i][j]
        float* Ob = mb + oi[s] * BUF;
        if (em[s]) mm8x4<false, true>(TAt, nullptr, MC, Ob, ry, cx, 0.f);
        else       mm8x4<false, false>(TAt, nullptr, MC, Ob, ry, cx, 0.f);
        __syncthreads();

        if (s == 6) {
            // rho2 = S + dt*PDP -> ST ; out-partial = S + dt/6*T + 2dt/3*PDP -> SB
            const float c1 = dt / 6.0f, c2 = 2.0f * dt / 3.0f;
            for (int m = 0; m < 2; ++m) {
                float* R0m = sm + m * 5 * BUF;          // holds T
                float* BDm = R0m + 2 * BUF;             // PDP
                float* STm = R0m + 3 * BUF;
                float* SBm = R0m + 4 * BUF;             // S
#pragma unroll
                for (int e = tid * 4; e < NB * NB; e += 1024) {
                    int idx = (e >> 6) * SSTR + (e & 63);
                    float4 sv = *(float4*)(SBm + idx);
                    float4 dv = *(float4*)(BDm + idx);
                    float4 tv = *(float4*)(R0m + idx);
                    float4 r2, ob;
                    r2.x = fmaf(dt, dv.x, sv.x);
                    r2.y = fmaf(dt, dv.y, sv.y);
                    r2.z = fmaf(dt, dv.z, sv.z);
                    r2.w = fmaf(dt, dv.w, sv.w);
                    ob.x = sv.x + c1 * tv.x + c2 * dv.x;
                    ob.y = sv.y + c1 * tv.y + c2 * dv.y;
                    ob.z = sv.z + c1 * tv.z + c2 * dv.z;
                    ob.w = sv.w + c1 * tv.w + c2 * dv.w;
                    *(float4*)(STm + idx) = r2;
                    *(float4*)(SBm + idx) = ob;
                }
            }
            __syncthreads();
        }
    }

    // final: out = SB + dt/6 * D1(BD)
    {
        const float c1 = dt / 6.0f;
        for (int m = 0; m < 2; ++m) {
            float* BDm = sm + m * 5 * BUF + 2 * BUF;
            float* SBm = sm + m * 5 * BUF + 4 * BUF;
            float* og = out + (2 * b + m) * (NB * NB);
#pragma unroll
            for (int e = tid * 4; e < NB * NB; e += 1024) {
                int idx = (e >> 6) * SSTR + (e & 63);
                float4 sv = *(float4*)(SBm + idx);
                float4 dv = *(float4*)(BDm + idx);
                float4 o;
                o.x = fmaf(c1, dv.x, sv.x);
                o.y = fmaf(c1, dv.y, sv.y);
                o.z = fmaf(c1, dv.z, sv.z);
                o.w = fmaf(c1, dv.w, sv.w);
                *(float4*)(og + e) = o;
            }
        }
    }
}

extern "C" void kernel_launch(void* const* d_in, const int* in_sizes, int n_in,
                              void* d_out, int out_size)
{
    const float* rho0   = (const float*)d_in[0];
    const float* U_half = (const float*)d_in[1];
    const float* U_one  = (const float*)d_in[2];
    const float* L0     = (const float*)d_in[3];
    const float* Lh     = (const float*)d_in[4];
    const float* L1     = (const float*)d_in[5];
    float* out = (float*)d_out;

    const int Bn = in_sizes[0] / (NB * NB);

    cudaFuncSetAttribute(krk_pre,  cudaFuncAttributeMaxDynamicSharedMemorySize, 3 * BUF * 4);
    cudaFuncSetAttribute(krk_main, cudaFuncAttributeMaxDynamicSharedMemorySize, 11 * BUF * 4);

    krk_pre<<<1, 256, 3 * BUF * 4>>>(U_half, U_one, Lh);
    krk_main<<<Bn / 2, 256, 11 * BUF * 4>>>(rho0, U_half, U_one, L0, L1, out);
}